// round 13
// baseline (speedup 1.0000x reference)
#include <cuda_runtime.h>
#include <cstdint>

#define NC 256
#define NH 256
#define NW 256
#define NBOX 100
#define SLICES 8                       // writer blocks per channel
#define ROWS_PER_SLICE (NH / SLICES)   // 32
#define TILE_F4 (ROWS_PER_SLICE * NW / 4)   // 2048 float4 per block

__device__ float4   g_coef[NC];   // A, B1, B2, D per channel
__device__ unsigned g_flag[NC];   // publish flags (self-resetting)
__device__ unsigned g_cons[NC];   // per-channel consume counters (self-resetting)

// ---------------------------------------------------------------------------
// ONE kernel, 2048 blocks. Blocks 0..255 produce coef[bid] (box math + gather
// + reduce), publish via fenced flag. Every block waits only on flag[bid>>3],
// then streams its 32-row slice at the L2 write cap. No global barrier.
//   out[c,h,w] = w*(w*A - B1) + h*(h*A - B2) + D
// nonzero(size=100, fill=0) == each selected box once + (100-cnt) copies of box 0.
// ---------------------------------------------------------------------------
__global__ __launch_bounds__(256)
void fused_kernel(const float* __restrict__ boxes,
                  const float* __restrict__ scores,
                  const float* __restrict__ feat,
                  float4* __restrict__ out) {
    __shared__ float4 red[128];
    __shared__ int    s_pc[4];
    __shared__ float4 s_k;
    const int tid = threadIdx.x;
    const int bid = blockIdx.x;
    const int c   = bid >> 3;

    // ================= Producer phase (blocks 0..255 only) =================
    if (bid < NC) {
        int m = 0;
        if (tid < NBOX) m = (scores[tid] > 0.0f) ? 1 : 0;
        unsigned bal = __ballot_sync(0xffffffffu, m);
        if (tid < 128 && (tid & 31) == 0) s_pc[tid >> 5] = __popc(bal);
        __syncthreads();
        const int cnt = s_pc[0] + s_pc[1] + s_pc[2] + s_pc[3];

        float4 acc = make_float4(0.f, 0.f, 0.f, 0.f);
        if (tid < NBOX) {
            const float4* b4 = (const float4*)(boxes + (size_t)tid * 24);
            float4 v0 = b4[0], v1 = b4[1], v2 = b4[2], v3 = b4[3], v4 = b4[4], v5 = b4[5];
            // corners are (x,y,z) triples: x at 0,3,..,21 ; y at 1,4,..,22
            float xs[8] = {v0.x, v0.w, v1.z, v2.y, v3.x, v3.w, v4.z, v5.y};
            float ys[8] = {v0.y, v1.x, v1.w, v2.z, v3.y, v4.x, v4.w, v5.z};
            float lx = xs[0], rx = xs[0], ly = ys[0], ry = ys[0];
            #pragma unroll
            for (int k = 1; k < 8; k++) {
                lx = fminf(lx, xs[k]); rx = fmaxf(rx, xs[k]);
                ly = fminf(ly, ys[k]); ry = fmaxf(ry, ys[k]);
            }
            float cx  = ((lx + rx) * 0.5f + 128.0f) / 160.0f;
            float cy  = ((ly + ry) * 0.5f + 128.0f) / 160.0f;
            float bev = ((ry - ly) / 160.0f) * ((rx - lx) / 160.0f);
            float a   = 1.0f / (2.0f * bev * bev);
            float r2  = cx * cx + cy * cy;

            // bilinear grid_sample (zero pad, align_corners=False)
            float ix = ((cx + 1.0f) * (float)NW - 1.0f) * 0.5f;
            float iy = ((cy + 1.0f) * (float)NH - 1.0f) * 0.5f;
            float x0f = floorf(ix), y0f = floorf(iy);
            float wx1 = ix - x0f, wx0 = 1.0f - wx1;
            float wy1 = iy - y0f, wy0 = 1.0f - wy1;
            int x0 = (int)x0f, y0 = (int)y0f, x1 = x0 + 1, y1 = y0 + 1;
            bool vx0 = (x0 >= 0 && x0 < NW), vx1 = (x1 >= 0 && x1 < NW);
            bool vy0 = (y0 >= 0 && y0 < NH), vy1 = (y1 >= 0 && y1 < NH);
            int px0 = min(max(x0, 0), NW - 1), px1 = min(max(x1, 0), NW - 1);
            int py0 = min(max(y0, 0), NH - 1), py1 = min(max(y1, 0), NH - 1);
            float w00 = (vx0 && vy0) ? wx0 * wy0 : 0.0f;
            float w10 = (vx1 && vy0) ? wx1 * wy0 : 0.0f;
            float w01 = (vx0 && vy1) ? wx0 * wy1 : 0.0f;
            float w11 = (vx1 && vy1) ? wx1 * wy1 : 0.0f;

            const float* fc = feat + (size_t)bid * NH * NW;
            float v = w00 * __ldg(fc + py0 * NW + px0)
                    + w10 * __ldg(fc + py0 * NW + px1)
                    + w01 * __ldg(fc + py1 * NW + px0)
                    + w11 * __ldg(fc + py1 * NW + px1);

            float mult = (tid == 0) ? (float)(m + NBOX - cnt) : (float)m;
            float ta = v * a * mult;
            acc = make_float4(ta, ta * cx, ta * cy, ta * r2);
        }
        if (tid < 128) red[tid] = acc;
        __syncthreads();
        #pragma unroll
        for (int s = 64; s > 0; s >>= 1) {
            if (tid < s) {
                float4 u = red[tid], v = red[tid + s];
                red[tid] = make_float4(u.x + v.x, u.y + v.y, u.z + v.z, u.w + v.w);
            }
            __syncthreads();
        }
        if (tid == 0) {
            const float inv = 1.0f / (float)NBOX;
            float4 r = red[0];
            g_coef[bid] = make_float4(r.x * inv, 2.0f * r.y * inv,
                                      2.0f * r.z * inv, r.w * inv);
            __threadfence();                         // coef before flag
            *(volatile unsigned*)&g_flag[bid] = 1u;  // publish
        }
    }

    // ================= Consumer wait (every block, own channel only) =======
    if (tid == 0) {
        while (*(volatile unsigned*)&g_flag[c] == 0u) __nanosleep(64);
        __threadfence();                             // acquire
        s_k = g_coef[c];
        // self-resetting bookkeeping: 8th consumer of channel c zeroes state
        unsigned old = atomicAdd(&g_cons[c], 1u);
        if (old == SLICES - 1u) {
            *(volatile unsigned*)&g_flag[c] = 0u;
            *(volatile unsigned*)&g_cons[c] = 0u;
        }
    }
    __syncthreads();

    // ================= Writer phase (all blocks) ===========================
    const float A = s_k.x, B1 = s_k.y, B2 = s_k.z, D = s_k.w;
    const int slice = bid & 7;
    float4* oc = out + (size_t)bid * TILE_F4;
    const float w0 = (float)((tid & 63) * 4);
    const float pw0 = (w0      ) * fmaf(w0,       A, -B1);
    const float pw1 = (w0 + 1.f) * fmaf(w0 + 1.f, A, -B1);
    const float pw2 = (w0 + 2.f) * fmaf(w0 + 2.f, A, -B1);
    const float pw3 = (w0 + 3.f) * fmaf(w0 + 3.f, A, -B1);

    #pragma unroll
    for (int k = 0; k < TILE_F4 / 256; k++) {   // 8 iters
        int   i    = k * 256 + tid;
        float hf   = (float)(slice * ROWS_PER_SLICE + (i >> 6));
        float base = fmaf(hf, fmaf(hf, A, -B2), D);
        oc[i] = make_float4(pw0 + base, pw1 + base, pw2 + base, pw3 + base);
    }
}

// ---------------------------------------------------------------------------
extern "C" void kernel_launch(void* const* d_in, const int* in_sizes, int n_in,
                              void* d_out, int out_size) {
    const float* boxes  = (const float*)d_in[0];   // [100,8,3]
    const float* scores = (const float*)d_in[1];   // [100]
    const float* feat   = (const float*)d_in[2];   // [1,256,256,256]

    fused_kernel<<<NC * SLICES, 256>>>(boxes, scores, feat, (float4*)d_out);
    (void)in_sizes; (void)n_in; (void)out_size;
}

// round 14
// speedup vs baseline: 1.2261x; 1.2261x over previous
#include <cuda_runtime.h>
#include <cstdint>

#define NC 256
#define NH 256
#define NW 256
#define NBOX 100
#define SLICES 16                      // writer blocks per channel (sweep: 1024->13.5, 2048->12.7, try 4096)
#define ROWS_PER_SLICE (NH / SLICES)   // 16
#define TILE_F4 (ROWS_PER_SLICE * NW / 4)   // 1024 float4 per block

__device__ float4 g_coef[NC];          // A, B1, B2, D per channel

// ---------------------------------------------------------------------------
// Kernel 1: per-channel coefficients (one block per channel, fully parallel).
// nonzero(size=100, fill=0) == each selected box once + (100-cnt) copies of box 0.
// ---------------------------------------------------------------------------
__global__ __launch_bounds__(128)
void coef_kernel(const float* __restrict__ boxes,
                 const float* __restrict__ scores,
                 const float* __restrict__ feat) {
    __shared__ float4 red[128];
    __shared__ int    s_pc[4];
    const int tid = threadIdx.x;
    const int c   = blockIdx.x;

    int m = 0;
    if (tid < NBOX) m = (scores[tid] > 0.0f) ? 1 : 0;
    unsigned bal = __ballot_sync(0xffffffffu, m);
    if ((tid & 31) == 0) s_pc[tid >> 5] = __popc(bal);
    __syncthreads();
    const int cnt = s_pc[0] + s_pc[1] + s_pc[2] + s_pc[3];

    float4 acc = make_float4(0.f, 0.f, 0.f, 0.f);
    if (tid < NBOX) {
        const float4* b4 = (const float4*)(boxes + (size_t)tid * 24);
        float4 v0 = b4[0], v1 = b4[1], v2 = b4[2], v3 = b4[3], v4 = b4[4], v5 = b4[5];
        // corners are (x,y,z) triples: x at 0,3,..,21 ; y at 1,4,..,22
        float xs[8] = {v0.x, v0.w, v1.z, v2.y, v3.x, v3.w, v4.z, v5.y};
        float ys[8] = {v0.y, v1.x, v1.w, v2.z, v3.y, v4.x, v4.w, v5.z};
        float lx = xs[0], rx = xs[0], ly = ys[0], ry = ys[0];
        #pragma unroll
        for (int k = 1; k < 8; k++) {
            lx = fminf(lx, xs[k]); rx = fmaxf(rx, xs[k]);
            ly = fminf(ly, ys[k]); ry = fmaxf(ry, ys[k]);
        }
        float cx  = ((lx + rx) * 0.5f + 128.0f) / 160.0f;
        float cy  = ((ly + ry) * 0.5f + 128.0f) / 160.0f;
        float bev = ((ry - ly) / 160.0f) * ((rx - lx) / 160.0f);
        float a   = 1.0f / (2.0f * bev * bev);
        float r2  = cx * cx + cy * cy;

        // bilinear grid_sample (zero pad, align_corners=False)
        float ix = ((cx + 1.0f) * (float)NW - 1.0f) * 0.5f;
        float iy = ((cy + 1.0f) * (float)NH - 1.0f) * 0.5f;
        float x0f = floorf(ix), y0f = floorf(iy);
        float wx1 = ix - x0f, wx0 = 1.0f - wx1;
        float wy1 = iy - y0f, wy0 = 1.0f - wy1;
        int x0 = (int)x0f, y0 = (int)y0f, x1 = x0 + 1, y1 = y0 + 1;
        bool vx0 = (x0 >= 0 && x0 < NW), vx1 = (x1 >= 0 && x1 < NW);
        bool vy0 = (y0 >= 0 && y0 < NH), vy1 = (y1 >= 0 && y1 < NH);
        int px0 = min(max(x0, 0), NW - 1), px1 = min(max(x1, 0), NW - 1);
        int py0 = min(max(y0, 0), NH - 1), py1 = min(max(y1, 0), NH - 1);
        float w00 = (vx0 && vy0) ? wx0 * wy0 : 0.0f;
        float w10 = (vx1 && vy0) ? wx1 * wy0 : 0.0f;
        float w01 = (vx0 && vy1) ? wx0 * wy1 : 0.0f;
        float w11 = (vx1 && vy1) ? wx1 * wy1 : 0.0f;

        const float* fc = feat + (size_t)c * NH * NW;
        float v = w00 * __ldg(fc + py0 * NW + px0)
                + w10 * __ldg(fc + py0 * NW + px1)
                + w01 * __ldg(fc + py1 * NW + px0)
                + w11 * __ldg(fc + py1 * NW + px1);

        float mult = (tid == 0) ? (float)(m + NBOX - cnt) : (float)m;
        float ta = v * a * mult;
        acc = make_float4(ta, ta * cx, ta * cy, ta * r2);
    }
    red[tid] = acc;
    __syncthreads();
    #pragma unroll
    for (int s = 64; s > 0; s >>= 1) {
        if (tid < s) {
            float4 u = red[tid], v = red[tid + s];
            red[tid] = make_float4(u.x + v.x, u.y + v.y, u.z + v.z, u.w + v.w);
        }
        __syncthreads();
    }
    if (tid == 0) {
        const float inv = 1.0f / (float)NBOX;
        float4 r = red[0];
        g_coef[c] = make_float4(r.x * inv, 2.0f * r.y * inv, 2.0f * r.z * inv, r.w * inv);
        __threadfence();   // g_coef visible before dependents may read it
    }
    __syncthreads();
    asm volatile("griddepcontrol.launch_dependents;");
}

// ---------------------------------------------------------------------------
// Kernel 2: pure streaming STG.128 writer — at the L2 write-port cap.
// 4096 blocks x 256 threads, 4 STG.128 per thread (deeper chip-wide store MLP).
//   out[c,h,w] = w*(w*A - B1) + h*(h*A - B2) + D
// ---------------------------------------------------------------------------
__global__ __launch_bounds__(256)
void out_kernel(float4* __restrict__ out) {
    asm volatile("griddepcontrol.wait;" ::: "memory");
    const int tid   = threadIdx.x;
    const int c     = blockIdx.x >> 4;
    const int slice = blockIdx.x & 15;

    const float4 k4 = __ldg(&g_coef[c]);
    const float A = k4.x, B1 = k4.y, B2 = k4.z, D = k4.w;

    float4* oc = out + (size_t)blockIdx.x * TILE_F4;
    const float w0 = (float)((tid & 63) * 4);
    // w-polynomial invariant across the rows this thread touches
    const float pw0 = (w0      ) * fmaf(w0,       A, -B1);
    const float pw1 = (w0 + 1.f) * fmaf(w0 + 1.f, A, -B1);
    const float pw2 = (w0 + 2.f) * fmaf(w0 + 2.f, A, -B1);
    const float pw3 = (w0 + 3.f) * fmaf(w0 + 3.f, A, -B1);

    #pragma unroll
    for (int k = 0; k < TILE_F4 / 256; k++) {   // 4 iters
        int   i    = k * 256 + tid;
        float hf   = (float)(slice * ROWS_PER_SLICE + (i >> 6));
        float base = fmaf(hf, fmaf(hf, A, -B2), D);
        oc[i] = make_float4(pw0 + base, pw1 + base, pw2 + base, pw3 + base);
    }
}

// ---------------------------------------------------------------------------
extern "C" void kernel_launch(void* const* d_in, const int* in_sizes, int n_in,
                              void* d_out, int out_size) {
    const float* boxes  = (const float*)d_in[0];   // [100,8,3]
    const float* scores = (const float*)d_in[1];   // [100]
    const float* feat   = (const float*)d_in[2];   // [1,256,256,256]

    coef_kernel<<<NC, 128>>>(boxes, scores, feat);

    cudaLaunchConfig_t cfg = {};
    cfg.gridDim  = dim3(NC * SLICES);   // 4096 blocks
    cfg.blockDim = dim3(256);
    cfg.dynamicSmemBytes = 0;
    cfg.stream = 0;
    cudaLaunchAttribute attr[1];
    attr[0].id = cudaLaunchAttributeProgrammaticStreamSerialization;
    attr[0].val.programmaticStreamSerializationAllowed = 1;
    cfg.attrs = attr;
    cfg.numAttrs = 1;
    cudaLaunchKernelEx(&cfg, out_kernel, (float4*)d_out);

    (void)in_sizes; (void)n_in; (void)out_size;
}

// round 15
// speedup vs baseline: 1.2427x; 1.0136x over previous
#include <cuda_runtime.h>
#include <cstdint>

#define NC 256
#define NH 256
#define NW 256
#define NBOX 100
#define SLICES 4                       // writer slices per channel -> 1024 blocks
#define ROWS_PER_SLICE (NH / SLICES)   // 64
#define TILE_F4 (ROWS_PER_SLICE * NW / 4)   // 4096 float4 per block

// ---------------------------------------------------------------------------
// ONE kernel, 1024 independent blocks (4 per channel). Each block redundantly
// computes its channel's 4 coefficients with a cheap prologue, then streams
// its 64-row slice at the L2 write cap. No inter-block sync, one graph node.
//   out[c,h,w] = w*(w*A - B1) + h*(h*A - B2) + D
// nonzero(size=100, fill=0) == each selected box once + (100-cnt) copies of box 0.
// ---------------------------------------------------------------------------
__global__ __launch_bounds__(256)
void fused_kernel(const float* __restrict__ boxes,
                  const float* __restrict__ scores,
                  const float* __restrict__ feat,
                  float4* __restrict__ out) {
    __shared__ float  s_box[NBOX * 24];    // staged box corners (9.6 KB)
    __shared__ float4 s_kv[NBOX];          // per-box (am, am*2cx, am*2cy, am*r2)
    __shared__ float  s_w[NBOX][4];        // bilinear weights
    __shared__ int    s_o[NBOX][4];        // gather offsets
    __shared__ float4 red[256];
    __shared__ int    s_pc[4];

    const int tid = threadIdx.x;
    const int c     = blockIdx.x >> 2;
    const int slice = blockIdx.x & 3;

    // ---- Phase A: scores ballot (warps 0-3) + cooperative box staging ----
    if (tid < 128) {
        int m = (tid < NBOX) ? ((scores[tid] > 0.0f) ? 1 : 0) : 0;
        unsigned bal = __ballot_sync(0xffffffffu, m);
        if ((tid & 31) == 0) s_pc[tid >> 5] = __popc(bal);
    }
    // coalesced: 600 float4 = 2400 floats staged by all 256 threads
    {
        const float4* src = (const float4*)boxes;
        float4*       dst = (float4*)s_box;
        #pragma unroll
        for (int i = tid; i < NBOX * 6; i += 256) dst[i] = src[i];
    }
    __syncthreads();
    const int cnt = s_pc[0] + s_pc[1] + s_pc[2] + s_pc[3];

    // ---- Phase B: per-box params from smem (threads 0..99) ----
    if (tid < NBOX) {
        const float* b = s_box + tid * 24;
        float lx = b[0], rx = b[0], ly = b[1], ry = b[1];
        #pragma unroll
        for (int k = 1; k < 8; k++) {
            float x = b[3 * k], y = b[3 * k + 1];
            lx = fminf(lx, x); rx = fmaxf(rx, x);
            ly = fminf(ly, y); ry = fmaxf(ry, y);
        }
        float cx  = ((lx + rx) * 0.5f + 128.0f) / 160.0f;
        float cy  = ((ly + ry) * 0.5f + 128.0f) / 160.0f;
        float bev = ((ry - ly) / 160.0f) * ((rx - lx) / 160.0f);
        float a   = 1.0f / (2.0f * bev * bev);

        float m    = (scores[tid] > 0.0f) ? 1.0f : 0.0f;
        float mult = (tid == 0) ? (m + (float)(NBOX - cnt)) : m;
        float am   = a * mult * (1.0f / (float)NBOX);
        s_kv[tid]  = make_float4(am, am * 2.0f * cx, am * 2.0f * cy,
                                 am * (cx * cx + cy * cy));

        // bilinear grid_sample (zero pad, align_corners=False)
        float ix = ((cx + 1.0f) * (float)NW - 1.0f) * 0.5f;
        float iy = ((cy + 1.0f) * (float)NH - 1.0f) * 0.5f;
        float x0f = floorf(ix), y0f = floorf(iy);
        float wx1 = ix - x0f, wx0 = 1.0f - wx1;
        float wy1 = iy - y0f, wy0 = 1.0f - wy1;
        int x0 = (int)x0f, y0 = (int)y0f, x1 = x0 + 1, y1 = y0 + 1;
        bool vx0 = (x0 >= 0 && x0 < NW), vx1 = (x1 >= 0 && x1 < NW);
        bool vy0 = (y0 >= 0 && y0 < NH), vy1 = (y1 >= 0 && y1 < NH);
        int px0 = min(max(x0, 0), NW - 1), px1 = min(max(x1, 0), NW - 1);
        int py0 = min(max(y0, 0), NH - 1), py1 = min(max(y1, 0), NH - 1);
        s_w[tid][0] = (vx0 && vy0) ? wx0 * wy0 : 0.0f;  s_o[tid][0] = py0 * NW + px0;
        s_w[tid][1] = (vx1 && vy0) ? wx1 * wy0 : 0.0f;  s_o[tid][1] = py0 * NW + px1;
        s_w[tid][2] = (vx0 && vy1) ? wx0 * wy1 : 0.0f;  s_o[tid][2] = py1 * NW + px0;
        s_w[tid][3] = (vx1 && vy1) ? wx1 * wy1 : 0.0f;  s_o[tid][3] = py1 * NW + px1;
    }
    __syncthreads();

    // ---- Phase C: 400 (box,corner) pairs over 256 threads, then reduce ----
    const float* fc = feat + (size_t)c * NH * NW;
    float4 acc;
    {
        int n = tid >> 2, k = tid & 3;           // pair tid (tid < 256 < 400)
        float v = s_w[n][k] * __ldg(fc + s_o[n][k]);
        float4 kv = s_kv[n];
        acc = make_float4(v * kv.x, v * kv.y, v * kv.z, v * kv.w);
    }
    if (tid < 144) {                              // pairs 256..399
        int p = 256 + tid, n = p >> 2, k = p & 3;
        float v = s_w[n][k] * __ldg(fc + s_o[n][k]);
        float4 kv = s_kv[n];
        acc.x += v * kv.x; acc.y += v * kv.y; acc.z += v * kv.z; acc.w += v * kv.w;
    }
    red[tid] = acc;
    __syncthreads();
    #pragma unroll
    for (int s = 128; s > 0; s >>= 1) {
        if (tid < s) {
            float4 u = red[tid], v = red[tid + s];
            red[tid] = make_float4(u.x + v.x, u.y + v.y, u.z + v.z, u.w + v.w);
        }
        __syncthreads();
    }
    const float A  = red[0].x;
    const float B1 = red[0].y;
    const float B2 = red[0].z;
    const float D  = red[0].w;

    // ---- Phase D: streaming writer, 16 STG.128/thread ----
    float4* oc = out + (size_t)blockIdx.x * TILE_F4;
    const float w0 = (float)((tid & 63) * 4);
    const float pw0 = (w0      ) * fmaf(w0,       A, -B1);
    const float pw1 = (w0 + 1.f) * fmaf(w0 + 1.f, A, -B1);
    const float pw2 = (w0 + 2.f) * fmaf(w0 + 2.f, A, -B1);
    const float pw3 = (w0 + 3.f) * fmaf(w0 + 3.f, A, -B1);

    #pragma unroll
    for (int k = 0; k < TILE_F4 / 256; k++) {   // 16 iters
        int   i    = k * 256 + tid;
        float hf   = (float)(slice * ROWS_PER_SLICE + (i >> 6));
        float base = fmaf(hf, fmaf(hf, A, -B2), D);
        oc[i] = make_float4(pw0 + base, pw1 + base, pw2 + base, pw3 + base);
    }
}

// ---------------------------------------------------------------------------
extern "C" void kernel_launch(void* const* d_in, const int* in_sizes, int n_in,
                              void* d_out, int out_size) {
    const float* boxes  = (const float*)d_in[0];   // [100,8,3]
    const float* scores = (const float*)d_in[1];   // [100]
    const float* feat   = (const float*)d_in[2];   // [1,256,256,256]

    fused_kernel<<<NC * SLICES, 256>>>(boxes, scores, feat, (float4*)d_out);
    (void)in_sizes; (void)n_in; (void)out_size;
}